// round 2
// baseline (speedup 1.0000x reference)
#include <cuda_runtime.h>

// cumprod along dim 1 of a (ROWS, 8192) fp32 matrix.
// One CTA per row. Stage the row through swizzled shared memory so that
// both the global-memory phases (coalesced float4) and the per-thread
// contiguous register phases (strided) are conflict-free.

#define ROW_LEN      8192
#define THREADS      256
#define PER_THREAD   32                  // floats per thread
#define VECS_PT      8                   // float4 per thread
#define NVEC         (ROW_LEN / 4)       // 2048 float4 per row

// XOR swizzle on float4 index: permutes low 3 bits by bits [5:3].
// Linear phase (j = i*256 + t): within an 8-lane LDS/STS.128 phase group the
// low 3 bits stay a permutation of 0..7 -> conflict-free.
// Strided phase (j = 8*t + i): low bits become i ^ (t&7), distinct across the
// 8 lanes of a phase group -> conflict-free.
__device__ __forceinline__ int swz(int j) { return j ^ ((j >> 3) & 7); }

__global__ void __launch_bounds__(THREADS)
cumprod_dim1_kernel(const float* __restrict__ x, float* __restrict__ y) {
    __shared__ float4 buf[NVEC];          // 32 KB row buffer (in/out reuse)
    __shared__ float  warp_tot[THREADS / 32];

    const int t    = threadIdx.x;
    const int lane = t & 31;
    const int wid  = t >> 5;

    const size_t row_off = (size_t)blockIdx.x * ROW_LEN;
    const float4* __restrict__ xin  = reinterpret_cast<const float4*>(x + row_off);
    float4* __restrict__       yout = reinterpret_cast<float4*>(y + row_off);

    // ---- coalesced gmem -> swizzled smem ----
    #pragma unroll
    for (int i = 0; i < VECS_PT; i++) {
        int j = i * THREADS + t;
        buf[swz(j)] = xin[j];
    }
    __syncthreads();

    // ---- each thread: inclusive prefix product over its 32 contiguous elems ----
    float vals[PER_THREAD];
    #pragma unroll
    for (int i = 0; i < VECS_PT; i++) {
        float4 v = buf[swz(t * VECS_PT + i)];
        vals[i * 4 + 0] = v.x;
        vals[i * 4 + 1] = v.y;
        vals[i * 4 + 2] = v.z;
        vals[i * 4 + 3] = v.w;
    }
    float p = 1.0f;
    #pragma unroll
    for (int i = 0; i < PER_THREAD; i++) {
        p *= vals[i];
        vals[i] = p;                       // local inclusive prefix
    }

    // ---- warp-level inclusive scan (product) of per-thread totals ----
    float incl = p;
    #pragma unroll
    for (int o = 1; o < 32; o <<= 1) {
        float v = __shfl_up_sync(0xffffffffu, incl, o);
        if (lane >= o) incl *= v;
    }
    if (lane == 31) warp_tot[wid] = incl;
    __syncthreads();

    // ---- per-warp exclusive prefix (8 warps: every thread just multiplies) ----
    float wexcl = 1.0f;
    #pragma unroll
    for (int w = 0; w < THREADS / 32 - 1; w++) {
        float wt = warp_tot[w];
        if (w < wid) wexcl *= wt;
    }
    // exclusive within-warp prefix for this thread
    float lexcl = __shfl_up_sync(0xffffffffu, incl, 1);
    if (lane == 0) lexcl = 1.0f;
    const float prefix = wexcl * lexcl;

    // ---- scale and write back to own smem slots (private: no extra sync) ----
    #pragma unroll
    for (int i = 0; i < VECS_PT; i++) {
        float4 v;
        v.x = vals[i * 4 + 0] * prefix;
        v.y = vals[i * 4 + 1] * prefix;
        v.z = vals[i * 4 + 2] * prefix;
        v.w = vals[i * 4 + 3] * prefix;
        buf[swz(t * VECS_PT + i)] = v;
    }
    __syncthreads();

    // ---- swizzled smem -> coalesced gmem ----
    #pragma unroll
    for (int i = 0; i < VECS_PT; i++) {
        int j = i * THREADS + t;
        yout[j] = buf[swz(j)];
    }
}

extern "C" void kernel_launch(void* const* d_in, const int* in_sizes, int n_in,
                              void* d_out, int out_size) {
    const float* x = (const float*)d_in[0];
    float* y = (float*)d_out;
    const int rows = in_sizes[0] / ROW_LEN;   // 4096
    cumprod_dim1_kernel<<<rows, THREADS>>>(x, y);
}